// round 7
// baseline (speedup 1.0000x reference)
#include <cuda_runtime.h>
#include <math.h>

// ---------------- problem constants ----------------
#define CC   256
#define HH   128
#define WW   128
#define NB   4
#define HWW  (HH*WW)
#define KTOP 100

// conv tiling
#define TH   16
#define TW   16
#define OCT  64      // output channels per CTA
#define ICB  8       // input channels per smem stage
#define INROW 20     // padded input tile row stride (floats)
#define WDS  65      // padded dup-weight row stride (ull)

// output layout (concatenation of (prior_feature, prior_anchor, topk_score))
#define PF_ELEMS (NB*KTOP*CC)      // 102400
#define PA_OFF   PF_ELEMS
#define SC_OFF   (PF_ELEMS + NB*KTOP*11)  // 106800

typedef unsigned long long ull;

// packed 2xFP32 FMA (sm_100+)
__device__ __forceinline__ ull ffma2(ull a, ull b, ull c) {
    ull d;
    asm("fma.rn.f32x2 %0, %1, %2, %3;" : "=l"(d) : "l"(a), "l"(b), "l"(c));
    return d;
}
__device__ __forceinline__ ull pk(float lo, float hi) {
    ull d;
    asm("mov.b64 %0, {%1, %2};" : "=l"(d) : "f"(lo), "f"(hi));
    return d;
}
__device__ __forceinline__ float lo32(ull a) { return __uint_as_float((unsigned)a); }
__device__ __forceinline__ float hi32(ull a) { return __uint_as_float((unsigned)(a >> 32)); }

// ---------------- scratch (device globals; no allocs allowed) ----------------
__device__ float g_feat[(size_t)NB*CC*HWW];   // conv1 output (67 MB)
__device__ float g_plog[4*NB*HWW];            // per-ocgroup partial heatmap logits
__device__ int   g_tidx[NB*KTOP];             // topk indices

// ---------------- fused conv3x3 + BN + ReLU (+ optional 1x1 dot epilogue) ----
// MODE 0: out = relu(bn1(conv(bev, shared_w)))  -> g_feat
// MODE 1: partial_logits[ocg] = sum_{oc in grp} relu(bn2(conv(g_feat, obj_w1)))[oc]*w2[oc]
template<int MODE>
__global__ __launch_bounds__(256, 2)
void conv_kernel(const float* __restrict__ in, const float* __restrict__ wgt,
                 const float* __restrict__ bg, const float* __restrict__ bb,
                 const float* __restrict__ bm, const float* __restrict__ bv,
                 const float* __restrict__ w2)
{
    // input tile 8x18x20 floats (11520 B) + dup weights 72x65 ull (37440 B) = 48960 B
    __shared__ __align__(16) char smem_buf[ICB*18*INROW*4 + 72*WDS*8];
    float (*s_in)[18][INROW] = (float (*)[18][INROW])smem_buf;
    ull*   s_wd              = (ull*)(smem_buf + ICB*18*INROW*4);
    float (*s_red)[256]      = (float (*)[256])smem_buf;   // MODE 1, aliased after mainloop

    const int tx   = threadIdx.x;
    const int tile = blockIdx.x;          // 0..63 -> 8x8 spatial tiles
    const int ocg  = blockIdx.y;          // 0..3
    const int b    = blockIdx.z;          // 0..3
    const int ty0  = (tile >> 3) * TH;
    const int tx0  = (tile & 7) * TW;
    const int lane = tx & 31;
    const int o    = tx >> 5;             // warp id -> oc block of 8
    const int r    = lane >> 1;           // strip row within tile (0..15)
    const int xh   = lane & 1;            // strip half (x offset 0 or 8)

    ull acc[8][4];                        // [oc][pixel-pair]
    #pragma unroll
    for (int j = 0; j < 8; j++)
        #pragma unroll
        for (int p = 0; p < 4; p++) acc[j][p] = 0ull;

    const float* inb = (MODE == 0 ? in : (const float*)g_feat) + (size_t)b * CC * HWW;
    const float* wb  = wgt + (size_t)ocg * OCT * (CC*9);

    #pragma unroll 1
    for (int ic0 = 0; ic0 < CC; ic0 += ICB) {
        // ---- prefetch stage data into registers (hide DRAM latency behind prior compute)
        float vin[11];
        #pragma unroll
        for (int i = 0; i < 11; i++) {
            int e = tx + 256*i;
            float val = 0.f;
            if (e < ICB*18*18) {
                int ic = e / 324; int rr = e - ic*324;
                int yy = rr / 18; int xx = rr - yy*18;
                int gy = ty0 + yy - 1, gx = tx0 + xx - 1;
                if ((unsigned)gy < (unsigned)HH && (unsigned)gx < (unsigned)WW)
                    val = inb[(size_t)(ic0+ic)*HWW + gy*WW + gx];
            }
            vin[i] = val;
        }
        float vw[18];
        #pragma unroll
        for (int i = 0; i < 18; i++) {
            int e = tx + 256*i;
            int oc = e / 72; int rr = e - oc*72;
            vw[i] = wb[(size_t)oc*(CC*9) + ic0*9 + rr];
        }
        __syncthreads();   // prior stage consumers done
        #pragma unroll
        for (int i = 0; i < 11; i++) {
            int e = tx + 256*i;
            if (e < ICB*18*18) {
                int ic = e / 324; int rr = e - ic*324;
                int yy = rr / 18; int xx = rr - yy*18;
                s_in[ic][yy][xx] = vin[i];
            }
        }
        #pragma unroll
        for (int i = 0; i < 18; i++) {
            int e = tx + 256*i;
            int oc = e / 72; int rr = e - oc*72;
            unsigned u = __float_as_uint(vw[i]);
            s_wd[rr*WDS + oc] = ((ull)u << 32) | u;
        }
        __syncthreads();

        // ---- compute
        #pragma unroll 1
        for (int icc = 0; icc < ICB; icc++) {
            #pragma unroll
            for (int ky = 0; ky < 3; ky++) {
                const float4* quad = (const float4*)(&s_in[icc][r + ky][xh*8]);
                float4 A = quad[0], B = quad[1], C = quad[2];
                #pragma unroll
                for (int kx = 0; kx < 3; kx++) {
                    ull p0, p1, p2, p3;
                    if (kx == 0) { p0 = pk(A.x,A.y); p1 = pk(A.z,A.w); p2 = pk(B.x,B.y); p3 = pk(B.z,B.w); }
                    else if (kx == 1) { p0 = pk(A.y,A.z); p1 = pk(A.w,B.x); p2 = pk(B.y,B.z); p3 = pk(B.w,C.x); }
                    else { p0 = pk(A.z,A.w); p1 = pk(B.x,B.y); p2 = pk(B.z,B.w); p3 = pk(C.x,C.y); }
                    const ull* wrow = &s_wd[(icc*9 + ky*3 + kx)*WDS + o*8];
                    #pragma unroll
                    for (int j = 0; j < 8; j++) {
                        ull w = wrow[j];          // uniform across warp -> broadcast
                        acc[j][0] = ffma2(p0, w, acc[j][0]);
                        acc[j][1] = ffma2(p1, w, acc[j][1]);
                        acc[j][2] = ffma2(p2, w, acc[j][2]);
                        acc[j][3] = ffma2(p3, w, acc[j][3]);
                    }
                }
            }
        }
    }

    if (MODE == 0) {
        #pragma unroll
        for (int j = 0; j < 8; j++) {
            int oc = ocg*OCT + o*8 + j;
            float scl = bg[oc] * rsqrtf(bv[oc] + 1e-5f);
            float bi  = bb[oc] - bm[oc] * scl;
            float* gb = &g_feat[((size_t)b*CC + oc)*HWW + (size_t)(ty0 + r)*WW + tx0 + xh*8];
            #pragma unroll
            for (int p = 0; p < 4; p++) {
                float2 v;
                v.x = fmaxf(lo32(acc[j][p])*scl + bi, 0.f);
                v.y = fmaxf(hi32(acc[j][p])*scl + bi, 0.f);
                *(float2*)(gb + 2*p) = v;
            }
        }
    } else {
        float part[4][2];
        #pragma unroll
        for (int p = 0; p < 4; p++) { part[p][0] = 0.f; part[p][1] = 0.f; }
        #pragma unroll
        for (int j = 0; j < 8; j++) {
            int oc = ocg*OCT + o*8 + j;
            float scl = bg[oc] * rsqrtf(bv[oc] + 1e-5f);
            float bi  = bb[oc] - bm[oc] * scl;
            float wv2 = w2[oc];
            #pragma unroll
            for (int p = 0; p < 4; p++) {
                part[p][0] += fmaxf(lo32(acc[j][p])*scl + bi, 0.f) * wv2;
                part[p][1] += fmaxf(hi32(acc[j][p])*scl + bi, 0.f) * wv2;
            }
        }
        __syncthreads();   // done with smem tiles; safe to alias s_red
        #pragma unroll
        for (int p = 0; p < 4; p++) {
            int pix = r*16 + xh*8 + 2*p;
            s_red[o][pix]     = part[p][0];
            s_red[o][pix + 1] = part[p][1];
        }
        __syncthreads();
        float ssum = 0.f;
        #pragma unroll
        for (int g2 = 0; g2 < 8; g2++) ssum += s_red[g2][tx];  // fixed order: deterministic
        int pix = tx;
        g_plog[((size_t)ocg*NB + b)*HWW + (size_t)(ty0 + (pix>>4))*WW + tx0 + (pix&15)] = ssum;
    }
}

// ---------------- top-k (exact jax.lax.top_k semantics) ----------------
__global__ __launch_bounds__(1024)
void topk_kernel(const float* __restrict__ b2, float* __restrict__ out_sc)
{
    const int b    = blockIdx.x;
    const int tx   = threadIdx.x;
    const int lane = tx & 31, warp = tx >> 5;

    unsigned long long key[16];
    float lg[16];
    unsigned live = 0xFFFFu;
    const float bias = b2[0];

    #pragma unroll
    for (int k = 0; k < 16; k++) {
        int pix = tx + 1024*k;
        float v = g_plog[(0*NB + b)*HWW + pix] + g_plog[(1*NB + b)*HWW + pix]
                + g_plog[(2*NB + b)*HWW + pix] + g_plog[(3*NB + b)*HWW + pix] + bias;
        lg[k] = v;
        unsigned u = __float_as_uint(v);
        u = (u & 0x80000000u) ? ~u : (u | 0x80000000u);   // order-preserving map
        key[k] = ((unsigned long long)u << 32) | (unsigned)(0xFFFFFFFFu - (unsigned)pix);
    }

    __shared__ unsigned long long s_wmax[32];
    __shared__ unsigned long long s_best;

    for (int r = 0; r < KTOP; r++) {
        unsigned long long m = 0ull;
        #pragma unroll
        for (int k = 0; k < 16; k++)
            if (live & (1u << k)) { if (key[k] > m) m = key[k]; }
        #pragma unroll
        for (int off = 16; off; off >>= 1) {
            unsigned long long o2 = __shfl_down_sync(0xFFFFFFFFu, m, off);
            if (o2 > m) m = o2;
        }
        if (lane == 0) s_wmax[warp] = m;
        __syncthreads();
        if (warp == 0) {
            unsigned long long mm = s_wmax[lane];
            #pragma unroll
            for (int off = 16; off; off >>= 1) {
                unsigned long long o2 = __shfl_down_sync(0xFFFFFFFFu, mm, off);
                if (o2 > mm) mm = o2;
            }
            if (lane == 0) s_best = mm;
        }
        __syncthreads();
        unsigned long long best = s_best;
        #pragma unroll
        for (int k = 0; k < 16; k++) {
            if ((live & (1u << k)) && key[k] == best) {   // unique: idx packed in key
                live &= ~(1u << k);
                int pix = tx + 1024*k;
                g_tidx[b*KTOP + r]  = pix;
                out_sc[b*KTOP + r] = 1.0f / (1.0f + expf(-lg[k]));
            }
        }
        __syncthreads();
    }
}

// ---------------- per-query head: gather, FC->LN->ReLU->FC, small heads, anchor math ----
__global__ __launch_bounds__(256)
void head_kernel(const float* __restrict__ anchors,
                 const float* __restrict__ w1, const float* __restrict__ b1,
                 const float* __restrict__ lng, const float* __restrict__ lnb,
                 const float* __restrict__ w2, const float* __restrict__ b2,
                 const float* __restrict__ zw, const float* __restrict__ zb,
                 const float* __restrict__ dw, const float* __restrict__ db,
                 const float* __restrict__ yw, const float* __restrict__ yb,
                 const float* __restrict__ vw, const float* __restrict__ vb,
                 float* __restrict__ out_pf, float* __restrict__ out_pa,
                 const float* __restrict__ out_sc)
{
    const int q = blockIdx.x;            // 0..399
    const int b = q / KTOP, kq = q - b*KTOP;
    const int tx = threadIdx.x, lane = tx & 31, warp = tx >> 5;

    __shared__ float s_g[CC], s_x[CC], s_h[8], s_red[16];

    const int idx = g_tidx[q];
    s_g[tx] = g_feat[((size_t)b*CC + tx)*HWW + idx];
    __syncthreads();

    // GEMV1: x = g @ w1^T + b1   (warp w computes rows w*32..w*32+31)
    for (int jj = 0; jj < 32; jj++) {
        int j = warp*32 + jj;
        const float* wr = w1 + (size_t)j*CC;
        float pp = 0.f;
        #pragma unroll
        for (int m2 = 0; m2 < 8; m2++) pp += wr[lane + 32*m2] * s_g[lane + 32*m2];
        #pragma unroll
        for (int off = 16; off; off >>= 1) pp += __shfl_down_sync(0xFFFFFFFFu, pp, off);
        if (lane == 0) s_x[j] = pp + b1[j];
    }
    __syncthreads();

    // LayerNorm over 256
    float v = s_x[tx];
    float s1 = v, s2 = v*v;
    #pragma unroll
    for (int off = 16; off; off >>= 1) {
        s1 += __shfl_xor_sync(0xFFFFFFFFu, s1, off);
        s2 += __shfl_xor_sync(0xFFFFFFFFu, s2, off);
    }
    if (lane == 0) { s_red[warp] = s1; s_red[8 + warp] = s2; }
    __syncthreads();
    float t1 = 0.f, t2 = 0.f;
    #pragma unroll
    for (int w3 = 0; w3 < 8; w3++) { t1 += s_red[w3]; t2 += s_red[8 + w3]; }
    float mu  = t1 * (1.0f/CC);
    float var = t2 * (1.0f/CC) - mu*mu;
    float rstd = rsqrtf(var + 1e-5f);
    float xn = (v - mu) * rstd * lng[tx] + lnb[tx];
    __syncthreads();
    s_x[tx] = fmaxf(xn, 0.f);
    __syncthreads();

    // GEMV2 + score scale
    float sc = 1.f + out_sc[q];
    for (int jj = 0; jj < 32; jj++) {
        int j = warp*32 + jj;
        const float* wr = w2 + (size_t)j*CC;
        float pp = 0.f;
        #pragma unroll
        for (int m2 = 0; m2 < 8; m2++) pp += wr[lane + 32*m2] * s_x[lane + 32*m2];
        #pragma unroll
        for (int off = 16; off; off >>= 1) pp += __shfl_down_sync(0xFFFFFFFFu, pp, off);
        if (lane == 0) out_pf[(size_t)q*CC + j] = (pp + b2[j]) * sc;
    }

    // small heads: z(1) dim(3) yaw(2) vel(2) -> one per warp
    const float* hw; float hb;
    if (warp == 0)      { hw = zw;                  hb = zb[0]; }
    else if (warp < 4)  { hw = dw + (warp-1)*CC;    hb = db[warp-1]; }
    else if (warp < 6)  { hw = yw + (warp-4)*CC;    hb = yb[warp-4]; }
    else                { hw = vw + (warp-6)*CC;    hb = vb[warp-6]; }
    float pp = 0.f;
    #pragma unroll
    for (int m2 = 0; m2 < 8; m2++) pp += hw[lane + 32*m2] * s_g[lane + 32*m2];
    #pragma unroll
    for (int off = 16; off; off >>= 1) pp += __shfl_down_sync(0xFFFFFFFFu, pp, off);
    if (lane == 0) s_h[warp] = pp + hb;
    __syncthreads();

    if (tx == 0) {
        const float* pa = anchors + ((size_t)b*900 + kq)*11;
        float zp = s_h[0];
        float d0 = s_h[1], d1 = s_h[2], d2 = s_h[3];
        float y0 = tanhf(s_h[4]), y1 = tanhf(s_h[5]);
        float nrm = fmaxf(sqrtf(y0*y0 + y1*y1), 1e-6f);
        float ve0 = s_h[6], ve1 = s_h[7];
        int xs = idx & (WW-1), ys = idx >> 7;
        float* oa = out_pa + (size_t)q*11;
        oa[0]  = ((float)xs + 0.5f) * 0.8f + (-51.2f);
        oa[1]  = ((float)ys + 0.5f) * 0.8f + (-51.2f);
        oa[2]  = pa[2] + 0.5f * zp;
        oa[3]  = pa[3] + 0.2f * fminf(fmaxf(d0, -1.f), 1.f);
        oa[4]  = pa[4] + 0.2f * fminf(fmaxf(d1, -1.f), 1.f);
        oa[5]  = pa[5] + 0.2f * fminf(fmaxf(d2, -1.f), 1.f);
        oa[6]  = 0.7f*pa[6] + 0.3f*(y0 / nrm);
        oa[7]  = 0.7f*pa[7] + 0.3f*(y1 / nrm);
        oa[8]  = pa[8] + 0.2f * fminf(fmaxf(ve0, -2.f), 2.f);
        oa[9]  = pa[9] + 0.2f * fminf(fmaxf(ve1, -2.f), 2.f);
        oa[10] = pa[10];
    }
}

// ---------------- launch ----------------
extern "C" void kernel_launch(void* const* d_in, const int* in_sizes, int n_in,
                              void* d_out, int out_size)
{
    const float* bev      = (const float*)d_in[0];
    const float* anchors  = (const float*)d_in[1];
    const float* shared_w = (const float*)d_in[2];
    const float* bn1g = (const float*)d_in[3];
    const float* bn1b = (const float*)d_in[4];
    const float* bn1m = (const float*)d_in[5];
    const float* bn1v = (const float*)d_in[6];
    const float* obj_w1 = (const float*)d_in[7];
    const float* bn2g = (const float*)d_in[8];
    const float* bn2b = (const float*)d_in[9];
    const float* bn2m = (const float*)d_in[10];
    const float* bn2v = (const float*)d_in[11];
    const float* obj_w2 = (const float*)d_in[12];
    const float* obj_b2 = (const float*)d_in[13];
    const float* fp_w1  = (const float*)d_in[14];
    const float* fp_b1  = (const float*)d_in[15];
    const float* ln_g   = (const float*)d_in[16];
    const float* ln_b   = (const float*)d_in[17];
    const float* fp_w2  = (const float*)d_in[18];
    const float* fp_b2  = (const float*)d_in[19];
    const float* z_w    = (const float*)d_in[20];
    const float* z_b    = (const float*)d_in[21];
    const float* dim_w  = (const float*)d_in[22];
    const float* dim_b  = (const float*)d_in[23];
    const float* yaw_w  = (const float*)d_in[24];
    const float* yaw_b  = (const float*)d_in[25];
    const float* vel_w  = (const float*)d_in[26];
    const float* vel_b  = (const float*)d_in[27];

    float* out   = (float*)d_out;
    float* out_pf = out;
    float* out_pa = out + PA_OFF;
    float* out_sc = out + SC_OFF;

    dim3 cgrid(64, 4, NB);
    conv_kernel<0><<<cgrid, 256>>>(bev, shared_w, bn1g, bn1b, bn1m, bn1v, nullptr);
    conv_kernel<1><<<cgrid, 256>>>(nullptr, obj_w1, bn2g, bn2b, bn2m, bn2v, obj_w2);
    topk_kernel<<<NB, 1024>>>(obj_b2, out_sc);
    head_kernel<<<NB*KTOP, 256>>>(anchors, fp_w1, fp_b1, ln_g, ln_b, fp_w2, fp_b2,
                                  z_w, z_b, dim_w, dim_b, yaw_w, yaw_b, vel_w, vel_b,
                                  out_pf, out_pa, out_sc);
}

// round 8
// speedup vs baseline: 1.2695x; 1.2695x over previous
#include <cuda_runtime.h>
#include <math.h>

// ---------------- problem constants ----------------
#define CC   256
#define HH   128
#define WW   128
#define NB   4
#define HWW  (HH*WW)
#define KTOP 100

// conv tiling
#define TH   16
#define TW   16
#define OCT  64      // output channels per CTA
#define ICB  8       // input channels per smem stage
#define INS2 20      // padded smem row stride (in ull units) for dup input tile
#define WTS  68      // padded stride for transposed weight tile (floats; 272B = 16B-aligned)

// output layout (concatenation of (prior_feature, prior_anchor, topk_score))
#define PF_ELEMS (NB*KTOP*CC)      // 102400
#define PA_OFF   PF_ELEMS
#define SC_OFF   (PF_ELEMS + NB*KTOP*11)  // 106800

typedef unsigned long long ull;

// packed 2xFP32 FMA (sm_100+): d.lo = a.lo*b.lo + c.lo; d.hi likewise
__device__ __forceinline__ ull ffma2(ull a, ull b, ull c) {
    ull d;
    asm("fma.rn.f32x2 %0, %1, %2, %3;" : "=l"(d) : "l"(a), "l"(b), "l"(c));
    return d;
}
__device__ __forceinline__ float lo32(ull a) { return __uint_as_float((unsigned)a); }
__device__ __forceinline__ float hi32(ull a) { return __uint_as_float((unsigned)(a >> 32)); }

// ---------------- scratch (device globals; no allocs allowed) ----------------
__device__ float g_feat[(size_t)NB*CC*HWW];   // conv1 output (67 MB)
__device__ float g_plog[4*NB*HWW];            // per-ocgroup partial heatmap logits
__device__ int   g_tidx[NB*KTOP];             // topk indices

// ---------------- fused conv3x3 + BN + ReLU (+ optional 1x1 dot epilogue) ----
// MODE 0: out = relu(bn1(conv(bev, shared_w)))  -> g_feat
// MODE 1: partial_logits[ocg] = sum_{oc in grp} relu(bn2(conv(g_feat, obj_w1)))[oc]*w2[oc]
// Thread shape: 8 oc-pairs (16 oc) x 4 pixels. Warp = 16 oc x 128 px. CTA = 64 oc x 256 px.
template<int MODE>
__global__ __launch_bounds__(256, 2)
void conv_kernel(const float* __restrict__ in, const float* __restrict__ wgt,
                 const float* __restrict__ bg, const float* __restrict__ bb,
                 const float* __restrict__ bm, const float* __restrict__ bv,
                 const float* __restrict__ w2)
{
    // dup input tile 8x18x20 ull (23040 B) + transposed weights 72x68 f (19584 B) = 42624 B
    __shared__ __align__(16) char smem_buf[ICB*18*INS2*8 + 72*WTS*4];
    ull   (*s_in2)[18][INS2] = (ull (*)[18][INS2])smem_buf;
    float (*s_wT)[WTS]       = (float (*)[WTS])(smem_buf + ICB*18*INS2*8);
    float (*s_red)[256]      = (float (*)[256])smem_buf;   // MODE 1, aliased after mainloop

    const int tx   = threadIdx.x;
    const int tile = blockIdx.x;          // 0..63 -> 8x8 spatial tiles
    const int ocg  = blockIdx.y;          // 0..3
    const int b    = blockIdx.z;          // 0..3
    const int ty0  = (tile >> 3) * TH;
    const int tx0  = (tile & 7) * TW;
    const int p    = tx & 31;             // lane
    const int o    = tx >> 5;             // warp id
    const int ocq  = o & 3;               // oc block of 16 within CTA
    const int ph   = o >> 2;              // pixel half (0/1): 128 pixels each
    // thread's 4 pixels: pix_k = ph*128 + p + 32k -> row r0+2k, col c (fixed)
    const int r0   = ph*8 + (p >> 4);     // base row in 16x16 tile
    const int c    = p & 15;              // column in tile

    ull acc[8][4];                        // [oc-pair][pixel]
    #pragma unroll
    for (int j = 0; j < 8; j++)
        #pragma unroll
        for (int k = 0; k < 4; k++) acc[j][k] = 0ull;

    const float* inb = (MODE == 0 ? in : (const float*)g_feat) + (size_t)b * CC * HWW;
    const float* wb  = wgt + (size_t)ocg * OCT * (CC*9);

    #pragma unroll 1
    for (int ic0 = 0; ic0 < CC; ic0 += ICB) {
        __syncthreads();
        // stage input tile (zero-pad halo), duplicated into both f32x2 lanes
        for (int e = tx; e < ICB*18*18; e += 256) {
            int ic = e / 324; int rr = e - ic*324;
            int yy = rr / 18; int xx = rr - yy*18;
            int gy = ty0 + yy - 1, gx = tx0 + xx - 1;
            float val = 0.f;
            if ((unsigned)gy < (unsigned)HH && (unsigned)gx < (unsigned)WW)
                val = inb[(size_t)(ic0+ic)*HWW + gy*WW + gx];
            unsigned u = __float_as_uint(val);
            s_in2[ic][yy][xx] = ((ull)u << 32) | u;
        }
        // stage weights transposed: s_wT[icc*9+t][oc]
        for (int e = tx; e < OCT*ICB*9; e += 256) {
            int oc = e / 72; int rr = e - oc*72;
            s_wT[rr][oc] = wb[(size_t)oc*(CC*9) + ic0*9 + rr];
        }
        __syncthreads();

        #pragma unroll 1
        for (int icc = 0; icc < ICB; icc++) {
            #pragma unroll
            for (int t = 0; t < 9; t++) {
                const int ky = t / 3, kx = t - ky*3;
                // 8 weight oc-pairs as 4x LDS.128 broadcast (16B-aligned: row stride 272B, ocq*64B)
                ull w2p[8];
                const ulonglong2* wq = (const ulonglong2*)&s_wT[icc*9 + t][ocq*16];
                #pragma unroll
                for (int jj = 0; jj < 4; jj++) {
                    ulonglong2 wv = wq[jj];
                    w2p[2*jj]   = wv.x;
                    w2p[2*jj+1] = wv.y;
                }
                #pragma unroll
                for (int k = 0; k < 4; k++) {
                    ull iv = s_in2[icc][r0 + 2*k + ky][c + kx];
                    #pragma unroll
                    for (int j = 0; j < 8; j++)
                        acc[j][k] = ffma2(iv, w2p[j], acc[j][k]);
                }
            }
        }
    }

    if (MODE == 0) {
        #pragma unroll
        for (int j = 0; j < 8; j++) {
            #pragma unroll
            for (int h = 0; h < 2; h++) {
                int oc = ocg*OCT + ocq*16 + 2*j + h;
                float scl = bg[oc] * rsqrtf(bv[oc] + 1e-5f);
                float bi  = bb[oc] - bm[oc] * scl;
                #pragma unroll
                for (int k = 0; k < 4; k++) {
                    float a = h ? hi32(acc[j][k]) : lo32(acc[j][k]);
                    float val = fmaxf(a*scl + bi, 0.f);
                    g_feat[((size_t)b*CC + oc)*HWW + (size_t)(ty0 + r0 + 2*k)*WW + tx0 + c] = val;
                }
            }
        }
    } else {
        float part[4];
        #pragma unroll
        for (int k = 0; k < 4; k++) part[k] = 0.f;
        #pragma unroll
        for (int j = 0; j < 8; j++) {
            #pragma unroll
            for (int h = 0; h < 2; h++) {
                int oc = ocg*OCT + ocq*16 + 2*j + h;
                float scl = bg[oc] * rsqrtf(bv[oc] + 1e-5f);
                float bi  = bb[oc] - bm[oc] * scl;
                float wv2 = w2[oc];
                #pragma unroll
                for (int k = 0; k < 4; k++) {
                    float a = h ? hi32(acc[j][k]) : lo32(acc[j][k]);
                    part[k] += fmaxf(a*scl + bi, 0.f) * wv2;
                }
            }
        }
        __syncthreads();   // done reading smem tiles; safe to alias s_red
        #pragma unroll
        for (int k = 0; k < 4; k++) {
            int pix = ph*128 + p + 32*k;   // = (r0+2k)*16 + c
            s_red[ocq][pix] = (ocq == 0 && false) ? 0.f : part[k];  // each (ocq,pix) unique
        }
        // NOTE: two warps share same ocq per pixel half; (ocq,ph) disjoint pix -> unique writer
        __syncthreads();
        float ssum = 0.f;
        #pragma unroll
        for (int g2 = 0; g2 < 4; g2++) ssum += s_red[g2][tx];  // fixed order: deterministic
        g_plog[((size_t)ocg*NB + b)*HWW + (size_t)(ty0 + (tx>>4))*WW + tx0 + (tx&15)] = ssum;
    }
}

// ---------------- top-k (exact jax.lax.top_k semantics) ----------------
__global__ __launch_bounds__(1024)
void topk_kernel(const float* __restrict__ b2, float* __restrict__ out_sc)
{
    const int b    = blockIdx.x;
    const int tx   = threadIdx.x;
    const int lane = tx & 31, warp = tx >> 5;

    unsigned long long key[16];
    float lg[16];
    unsigned live = 0xFFFFu;
    const float bias = b2[0];

    #pragma unroll
    for (int k = 0; k < 16; k++) {
        int pix = tx + 1024*k;
        float v = g_plog[(0*NB + b)*HWW + pix] + g_plog[(1*NB + b)*HWW + pix]
                + g_plog[(2*NB + b)*HWW + pix] + g_plog[(3*NB + b)*HWW + pix] + bias;
        lg[k] = v;
        unsigned u = __float_as_uint(v);
        u = (u & 0x80000000u) ? ~u : (u | 0x80000000u);   // order-preserving map
        key[k] = ((unsigned long long)u << 32) | (unsigned)(0xFFFFFFFFu - (unsigned)pix);
    }

    __shared__ unsigned long long s_wmax[32];
    __shared__ unsigned long long s_best;

    for (int r = 0; r < KTOP; r++) {
        unsigned long long m = 0ull;
        #pragma unroll
        for (int k = 0; k < 16; k++)
            if (live & (1u << k)) { if (key[k] > m) m = key[k]; }
        #pragma unroll
        for (int off = 16; off; off >>= 1) {
            unsigned long long o2 = __shfl_down_sync(0xFFFFFFFFu, m, off);
            if (o2 > m) m = o2;
        }
        if (lane == 0) s_wmax[warp] = m;
        __syncthreads();
        if (warp == 0) {
            unsigned long long mm = s_wmax[lane];
            #pragma unroll
            for (int off = 16; off; off >>= 1) {
                unsigned long long o2 = __shfl_down_sync(0xFFFFFFFFu, mm, off);
                if (o2 > mm) mm = o2;
            }
            if (lane == 0) s_best = mm;
        }
        __syncthreads();
        unsigned long long best = s_best;
        #pragma unroll
        for (int k = 0; k < 16; k++) {
            if ((live & (1u << k)) && key[k] == best) {   // unique: idx packed in key
                live &= ~(1u << k);
                int pix = tx + 1024*k;
                g_tidx[b*KTOP + r]  = pix;
                out_sc[b*KTOP + r] = 1.0f / (1.0f + expf(-lg[k]));
            }
        }
        __syncthreads();
    }
}

// ---------------- per-query head: gather, FC->LN->ReLU->FC, small heads, anchor math ----
__global__ __launch_bounds__(256)
void head_kernel(const float* __restrict__ anchors,
                 const float* __restrict__ w1, const float* __restrict__ b1,
                 const float* __restrict__ lng, const float* __restrict__ lnb,
                 const float* __restrict__ w2, const float* __restrict__ b2,
                 const float* __restrict__ zw, const float* __restrict__ zb,
                 const float* __restrict__ dw, const float* __restrict__ db,
                 const float* __restrict__ yw, const float* __restrict__ yb,
                 const float* __restrict__ vw, const float* __restrict__ vb,
                 float* __restrict__ out_pf, float* __restrict__ out_pa,
                 const float* __restrict__ out_sc)
{
    const int q = blockIdx.x;            // 0..399
    const int b = q / KTOP, kq = q - b*KTOP;
    const int tx = threadIdx.x, lane = tx & 31, warp = tx >> 5;

    __shared__ float s_g[CC], s_x[CC], s_h[8], s_red[16];

    const int idx = g_tidx[q];
    s_g[tx] = g_feat[((size_t)b*CC + tx)*HWW + idx];
    __syncthreads();

    // GEMV1: x = g @ w1^T + b1   (warp w computes rows w*32..w*32+31)
    for (int jj = 0; jj < 32; jj++) {
        int j = warp*32 + jj;
        const float* wr = w1 + (size_t)j*CC;
        float pp = 0.f;
        #pragma unroll
        for (int m2 = 0; m2 < 8; m2++) pp += wr[lane + 32*m2] * s_g[lane + 32*m2];
        #pragma unroll
        for (int off = 16; off; off >>= 1) pp += __shfl_down_sync(0xFFFFFFFFu, pp, off);
        if (lane == 0) s_x[j] = pp + b1[j];
    }
    __syncthreads();

    // LayerNorm over 256
    float v = s_x[tx];
    float s1 = v, s2 = v*v;
    #pragma unroll
    for (int off = 16; off; off >>= 1) {
        s1 += __shfl_xor_sync(0xFFFFFFFFu, s1, off);
        s2 += __shfl_xor_sync(0xFFFFFFFFu, s2, off);
    }
    if (lane == 0) { s_red[warp] = s1; s_red[8 + warp] = s2; }
    __syncthreads();
    float t1 = 0.f, t2 = 0.f;
    #pragma unroll
    for (int w3 = 0; w3 < 8; w3++) { t1 += s_red[w3]; t2 += s_red[8 + w3]; }
    float mu  = t1 * (1.0f/CC);
    float var = t2 * (1.0f/CC) - mu*mu;
    float rstd = rsqrtf(var + 1e-5f);
    float xn = (v - mu) * rstd * lng[tx] + lnb[tx];
    __syncthreads();
    s_x[tx] = fmaxf(xn, 0.f);
    __syncthreads();

    // GEMV2 + score scale
    float sc = 1.f + out_sc[q];
    for (int jj = 0; jj < 32; jj++) {
        int j = warp*32 + jj;
        const float* wr = w2 + (size_t)j*CC;
        float pp = 0.f;
        #pragma unroll
        for (int m2 = 0; m2 < 8; m2++) pp += wr[lane + 32*m2] * s_x[lane + 32*m2];
        #pragma unroll
        for (int off = 16; off; off >>= 1) pp += __shfl_down_sync(0xFFFFFFFFu, pp, off);
        if (lane == 0) out_pf[(size_t)q*CC + j] = (pp + b2[j]) * sc;
    }

    // small heads: z(1) dim(3) yaw(2) vel(2) -> one per warp
    const float* hw; float hb;
    if (warp == 0)      { hw = zw;                  hb = zb[0]; }
    else if (warp < 4)  { hw = dw + (warp-1)*CC;    hb = db[warp-1]; }
    else if (warp < 6)  { hw = yw + (warp-4)*CC;    hb = yb[warp-4]; }
    else                { hw = vw + (warp-6)*CC;    hb = vb[warp-6]; }
    float pp = 0.f;
    #pragma unroll
    for (int m2 = 0; m2 < 8; m2++) pp += hw[lane + 32*m2] * s_g[lane + 32*m2];
    #pragma unroll
    for (int off = 16; off; off >>= 1) pp += __shfl_down_sync(0xFFFFFFFFu, pp, off);
    if (lane == 0) s_h[warp] = pp + hb;
    __syncthreads();

    if (tx == 0) {
        const float* pa = anchors + ((size_t)b*900 + kq)*11;
        float zp = s_h[0];
        float d0 = s_h[1], d1 = s_h[2], d2 = s_h[3];
        float y0 = tanhf(s_h[4]), y1 = tanhf(s_h[5]);
        float nrm = fmaxf(sqrtf(y0*y0 + y1*y1), 1e-6f);
        float ve0 = s_h[6], ve1 = s_h[7];
        int xs = idx & (WW-1), ys = idx >> 7;
        float* oa = out_pa + (size_t)q*11;
        oa[0]  = ((float)xs + 0.5f) * 0.8f + (-51.2f);
        oa[1]  = ((float)ys + 0.5f) * 0.8f + (-51.2f);
        oa[2]  = pa[2] + 0.5f * zp;
        oa[3]  = pa[3] + 0.2f * fminf(fmaxf(d0, -1.f), 1.f);
        oa[4]  = pa[4] + 0.2f * fminf(fmaxf(d1, -1.f), 1.f);
        oa[5]  = pa[5] + 0.2f * fminf(fmaxf(d2, -1.f), 1.f);
        oa[6]  = 0.7f*pa[6] + 0.3f*(y0 / nrm);
        oa[7]  = 0.7f*pa[7] + 0.3f*(y1 / nrm);
        oa[8]  = pa[8] + 0.2f * fminf(fmaxf(ve0, -2.f), 2.f);
        oa[9]  = pa[9] + 0.2f * fminf(fmaxf(ve1, -2.f), 2.f);
        oa[10] = pa[10];
    }
}

// ---------------- launch ----------------
extern "C" void kernel_launch(void* const* d_in, const int* in_sizes, int n_in,
                              void* d_out, int out_size)
{
    const float* bev      = (const float*)d_in[0];
    const float* anchors  = (const float*)d_in[1];
    const float* shared_w = (const float*)d_in[2];
    const float* bn1g = (const float*)d_in[3];
    const float* bn1b = (const float*)d_in[4];
    const float* bn1m = (const float*)d_in[5];
    const float* bn1v = (const float*)d_in[6];
    const float* obj_w1 = (const float*)d_in[7];
    const float* bn2g = (const float*)d_in[8];
    const float* bn2b = (const float*)d_in[9];
    const float* bn2m = (const float*)d_in[10];
    const float* bn2v = (const float*)d_in[11];
    const float* obj_w2 = (const float*)d_in[12];
    const float* obj_b2 = (const float*)d_in[13];
    const float* fp_w1  = (const float*)d_in[14];
    const float* fp_b1  = (const float*)d_in[15];
    const float* ln_g   = (const float*)d_in[16];
    const float* ln_b   = (const float*)d_in[17];
    const float* fp_w2  = (const float*)d_in[18];
    const float* fp_b2  = (const float*)d_in[19];
    const float* z_w    = (const float*)d_in[20];
    const float* z_b    = (const float*)d_in[21];
    const float* dim_w  = (const float*)d_in[22];
    const float* dim_b  = (const float*)d_in[23];
    const float* yaw_w  = (const float*)d_in[24];
    const float* yaw_b  = (const float*)d_in[25];
    const float* vel_w  = (const float*)d_in[26];
    const float* vel_b  = (const float*)d_in[27];

    float* out   = (float*)d_out;
    float* out_pf = out;
    float* out_pa = out + PA_OFF;
    float* out_sc = out + SC_OFF;

    dim3 cgrid(64, 4, NB);
    conv_kernel<0><<<cgrid, 256>>>(bev, shared_w, bn1g, bn1b, bn1m, bn1v, nullptr);
    conv_kernel<1><<<cgrid, 256>>>(nullptr, obj_w1, bn2g, bn2b, bn2m, bn2v, obj_w2);
    topk_kernel<<<NB, 1024>>>(obj_b2, out_sc);
    head_kernel<<<NB*KTOP, 256>>>(anchors, fp_w1, fp_b1, ln_g, ln_b, fp_w2, fp_b2,
                                  z_w, z_b, dim_w, dim_b, yaw_w, yaw_b, vel_w, vel_b,
                                  out_pf, out_pa, out_sc);
}